// round 7
// baseline (speedup 1.0000x reference)
#include <cuda_runtime.h>
#include <cuda_bf16.h>

#define BD      2
#define SEQ     2048
#define DM      768
#define NH      12
#define DK      64
#define MROWS   (BD*SEQ)
#define ATT_SCALE 0.125f

typedef __nv_bfloat16 bf16;

// ===========================================================================
// helpers
// ===========================================================================
__device__ __forceinline__ unsigned smem_u32(const void* p) {
    unsigned a;
    asm("{ .reg .u64 t; cvta.to.shared.u64 t, %1; cvt.u32.u64 %0, t; }"
        : "=r"(a) : "l"(p));
    return a;
}
__device__ __forceinline__ void ldsm4(unsigned& r0, unsigned& r1, unsigned& r2,
                                      unsigned& r3, unsigned a) {
    asm volatile("ldmatrix.sync.aligned.m8n8.x4.shared.b16 {%0,%1,%2,%3}, [%4];"
        : "=r"(r0), "=r"(r1), "=r"(r2), "=r"(r3) : "r"(a));
}
__device__ __forceinline__ void ldsm4t(unsigned& r0, unsigned& r1, unsigned& r2,
                                       unsigned& r3, unsigned a) {
    asm volatile("ldmatrix.sync.aligned.m8n8.x4.trans.shared.b16 {%0,%1,%2,%3}, [%4];"
        : "=r"(r0), "=r"(r1), "=r"(r2), "=r"(r3) : "r"(a));
}
__device__ __forceinline__ void mma_bf16(float* c, const unsigned* a,
                                         unsigned b0, unsigned b1) {
    asm volatile("mma.sync.aligned.m16n8k16.row.col.f32.bf16.bf16.f32 "
        "{%0,%1,%2,%3},{%4,%5,%6,%7},{%8,%9},{%0,%1,%2,%3};"
        : "+f"(c[0]), "+f"(c[1]), "+f"(c[2]), "+f"(c[3])
        : "r"(a[0]), "r"(a[1]), "r"(a[2]), "r"(a[3]), "r"(b0), "r"(b1));
}
__device__ __forceinline__ unsigned pack_hilo(float x, float y, unsigned& lo) {
    bf16 hx = __float2bfloat16(x), hy = __float2bfloat16(y);
    bf16 lx = __float2bfloat16(x - __bfloat162float(hx));
    bf16 ly = __float2bfloat16(y - __bfloat162float(hy));
    lo = (unsigned)__bfloat16_as_ushort(lx) | ((unsigned)__bfloat16_as_ushort(ly) << 16);
    return (unsigned)__bfloat16_as_ushort(hx) | ((unsigned)__bfloat16_as_ushort(hy) << 16);
}
#define CPA16(d, s) \
    asm volatile("cp.async.cg.shared.global [%0], [%1], 16;" :: "r"(d), "l"(s) : "memory")
#define CP_COMMIT() asm volatile("cp.async.commit_group;" ::: "memory")
#define CP_WAIT0()  asm volatile("cp.async.wait_group 0;" ::: "memory")

// ===========================================================================
// scratch
// ===========================================================================
__device__ bf16 g_xhi[MROWS*DM], g_xlo[MROWS*DM];
__device__ bf16 g_Whi[5*DM*DM],  g_Wlo[5*DM*DM];
__device__ bf16 g_Qhi[MROWS*DM], g_Qlo[MROWS*DM];
__device__ bf16 g_Khi[MROWS*DM], g_Klo[MROWS*DM];
__device__ bf16 g_Vhi[MROWS*DM], g_Vlo[MROWS*DM];
__device__ bf16 g_Mhi[MROWS*DM], g_Mlo[MROWS*DM];
__device__ bf16 g_Hhi[MROWS*DM], g_Hlo[MROWS*DM];

// ===========================================================================
// merged fp32 -> bf16 hi/lo splitter (one launch)
// ===========================================================================
#define N4X (MROWS*DM/4)
#define N4W (DM*DM/4)
__global__ void __launch_bounds__(256) cvt_all(
    const float* __restrict__ x,
    const float* __restrict__ Wq, const float* __restrict__ Wk,
    const float* __restrict__ Wv, const float* __restrict__ Wo,
    const float* __restrict__ Wf,
    bf16* __restrict__ xhi, bf16* __restrict__ xlo,
    bf16* __restrict__ Whi, bf16* __restrict__ Wlo)
{
    int i = blockIdx.x * blockDim.x + threadIdx.x;
    const float* src; bf16 *hi, *lo; int off;
    if (i < N4X) { src = x; hi = xhi; lo = xlo; off = i; }
    else {
        int j = i - N4X;
        if (j >= 5 * N4W) return;
        int w = j / N4W;
        off = j - w * N4W;
        src = (w == 0) ? Wq : (w == 1) ? Wk : (w == 2) ? Wv : (w == 3) ? Wo : Wf;
        hi = Whi + (size_t)w * (DM*DM);
        lo = Wlo + (size_t)w * (DM*DM);
    }
    float4 v = reinterpret_cast<const float4*>(src)[off];
    uint2 hp, lp;
    hp.x = pack_hilo(v.x, v.y, lp.x);
    hp.y = pack_hilo(v.z, v.w, lp.y);
    reinterpret_cast<uint2*>(hi)[off] = hp;
    reinterpret_cast<uint2*>(lo)[off] = lp;
}

// ===========================================================================
// GEMM: C[4096,768] = A @ W^T + bias (split-bf16 3-pass, cp.async 2-stage)
// Tile 128x128, K-chunk 32, 8 warps (4M x 2N), warp 32x64.
// ===========================================================================
#define GK  32                       // K-chunk (bf16 elems)
#define GLD 40                       // padded row stride (bf16), 80B rows
#define G_T  (128*GLD*2)             // 10240 B per single tile
#define G_AH 0
#define G_AL (1*G_T)
#define G_BH (2*G_T)
#define G_BL (3*G_T)
#define G_STAGE (4*G_T)              // 40960 B
#define GEMM_SMEM (2*G_STAGE)        // 81920 B

__device__ __forceinline__ void gemm_core(
    const bf16* __restrict__ Ahi, const bf16* __restrict__ Alo,
    const bf16* __restrict__ Bhi, const bf16* __restrict__ Blo,
    const float* __restrict__ bias,
    float* __restrict__ Cf, bf16* __restrict__ Chi, bf16* __restrict__ Clo)
{
    extern __shared__ char smc[];
    const int tid = threadIdx.x, lane = tid & 31, wid = tid >> 5;
    const int wm = wid >> 1, wn = wid & 1;
    const int row0 = blockIdx.y * 128, col0 = blockIdx.x * 128;
    const unsigned sb = smem_u32(smc);

    float acc[2][8][4];
    #pragma unroll
    for (int i = 0; i < 2; i++)
        #pragma unroll
        for (int j = 0; j < 8; j++)
            #pragma unroll
            for (int k = 0; k < 4; k++) acc[i][j][k] = 0.0f;

    auto issue = [&](int s, int kc) {
        unsigned stg = sb + s * G_STAGE;
        #pragma unroll
        for (int u = 0; u < 2; u++) {
            int idx = u * 256 + tid;          // 512 x 16B per tile
            int r = idx >> 2, c = idx & 3;
            unsigned d = (unsigned)(r * GLD + c * 8) * 2;
            const char* gA = (const char*)(Ahi + (size_t)(row0 + r) * DM + kc) + c * 16;
            const char* gAl = (const char*)(Alo + (size_t)(row0 + r) * DM + kc) + c * 16;
            const char* gB = (const char*)(Bhi + (size_t)(col0 + r) * DM + kc) + c * 16;
            const char* gBl = (const char*)(Blo + (size_t)(col0 + r) * DM + kc) + c * 16;
            CPA16(stg + G_AH + d, gA);
            CPA16(stg + G_AL + d, gAl);
            CPA16(stg + G_BH + d, gB);
            CPA16(stg + G_BL + d, gBl);
        }
    };

    issue(0, 0);
    CP_COMMIT();

    const int NC = DM / GK;   // 24
    for (int c = 0; c < NC; c++) {
        const int p = c & 1;
        CP_WAIT0();
        __syncthreads();
        if (c + 1 < NC) { issue(p ^ 1, (c + 1) * GK); CP_COMMIT(); }

        const unsigned stg = sb + p * G_STAGE;
        #pragma unroll
        for (int ks = 0; ks < 2; ks++) {
            const int kr = ks * 16;
            unsigned ah[2][4], al[2][4];
            #pragma unroll
            for (int mi = 0; mi < 2; mi++) {
                int m = wm * 32 + mi * 16 + (lane & 15);
                int kk = kr + (lane >> 4) * 8;
                ldsm4(ah[mi][0], ah[mi][1], ah[mi][2], ah[mi][3],
                      stg + G_AH + (m * GLD + kk) * 2);
                ldsm4(al[mi][0], al[mi][1], al[mi][2], al[mi][3],
                      stg + G_AL + (m * GLD + kk) * 2);
            }
            // process B in two halves of 2 ni2 (32 cols) to bound live regs
            #pragma unroll
            for (int half = 0; half < 2; half++) {
                unsigned bh[2][4], bl[2][4];
                #pragma unroll
                for (int j = 0; j < 2; j++) {
                    int ni2 = half * 2 + j;
                    int n = wn * 64 + ni2 * 16 + (lane >> 4) * 8 + (lane & 7);
                    int kk = kr + ((lane >> 3) & 1) * 8;
                    ldsm4(bh[j][0], bh[j][1], bh[j][2], bh[j][3],
                          stg + G_BH + (n * GLD + kk) * 2);
                    ldsm4(bl[j][0], bl[j][1], bl[j][2], bl[j][3],
                          stg + G_BL + (n * GLD + kk) * 2);
                }
                #pragma unroll
                for (int mi = 0; mi < 2; mi++)
                    #pragma unroll
                    for (int no = 0; no < 4; no++) {
                        unsigned* bhp = &bh[no >> 1][(no & 1) * 2];
                        unsigned* blp = &bl[no >> 1][(no & 1) * 2];
                        float* a = acc[mi][half * 4 + no];
                        mma_bf16(a, ah[mi], bhp[0], bhp[1]);
                        mma_bf16(a, ah[mi], blp[0], blp[1]);
                        mma_bf16(a, al[mi], bhp[0], bhp[1]);
                    }
            }
        }
    }

    #pragma unroll
    for (int mi = 0; mi < 2; mi++)
        #pragma unroll
        for (int ni = 0; ni < 8; ni++) {
            int row = row0 + wm * 32 + mi * 16 + (lane >> 2);
            int col = col0 + wn * 64 + ni * 8 + (lane & 3) * 2;
            float2 bv = *reinterpret_cast<const float2*>(&bias[col]);
            #pragma unroll
            for (int h = 0; h < 2; h++) {
                int r = row + h * 8;
                float vx = acc[mi][ni][h * 2 + 0] + bv.x;
                float vy = acc[mi][ni][h * 2 + 1] + bv.y;
                size_t off = (size_t)r * DM + col;
                if (Cf) *reinterpret_cast<float2*>(&Cf[off]) = make_float2(vx, vy);
                if (Chi) {
                    unsigned lo, hi = pack_hilo(vx, vy, lo);
                    *reinterpret_cast<unsigned*>(&Chi[off]) = hi;
                    *reinterpret_cast<unsigned*>(&Clo[off]) = lo;
                }
            }
        }
}

__global__ void __launch_bounds__(256, 2) mma_gemm(
    const bf16* __restrict__ Ahi, const bf16* __restrict__ Alo,
    const bf16* __restrict__ Bhi, const bf16* __restrict__ Blo,
    const float* __restrict__ bias,
    float* __restrict__ Cf, bf16* __restrict__ Chi, bf16* __restrict__ Clo)
{
    gemm_core(Ahi, Alo, Bhi, Blo, bias, Cf, Chi, Clo);
}

__global__ void __launch_bounds__(256, 2) qkv_gemm(
    const bf16* __restrict__ xhi, const bf16* __restrict__ xlo,
    const bf16* __restrict__ Whi, const bf16* __restrict__ Wlo,
    const float* __restrict__ bq, const float* __restrict__ bk,
    const float* __restrict__ bv,
    bf16* __restrict__ Qhi, bf16* __restrict__ Qlo,
    bf16* __restrict__ Khi, bf16* __restrict__ Klo,
    bf16* __restrict__ Vhi, bf16* __restrict__ Vlo)
{
    const int z = blockIdx.z;
    const int WN = DM * DM;
    const float* bias = (z == 0) ? bq : (z == 1) ? bk : bv;
    bf16* Chi = (z == 0) ? Qhi : (z == 1) ? Khi : Vhi;
    bf16* Clo = (z == 0) ? Qlo : (z == 1) ? Klo : Vlo;
    gemm_core(xhi, xlo, Whi + (size_t)z * WN, Wlo + (size_t)z * WN, bias,
              nullptr, Chi, Clo);
}

// ===========================================================================
// Attention: 128 Q-rows/block, 8 warps. S stays in registers; warps split the
// t-range; one cross-warp O reduction at the end. (unchanged from round 6)
// ===========================================================================
#define ALD 72
#define A_QH_B 0
#define A_QL_B 18432
#define A_STG_B 36864
#define A_KH_B 0
#define A_KL_B 9216
#define A_VH_B 18432
#define A_VL_B 27648
#define ATTN_SMEM (36864 + 2*36864)   // 110592
#define OLD 66

__global__ void __launch_bounds__(256) attn_mma(
    const bf16* __restrict__ Qhi, const bf16* __restrict__ Qlo,
    const bf16* __restrict__ Khi, const bf16* __restrict__ Klo,
    const bf16* __restrict__ Vhi, const bf16* __restrict__ Vlo,
    bf16* __restrict__ Mhi, bf16* __restrict__ Mlo)
{
    extern __shared__ char sma[];
    const int tid = threadIdx.x, lane = tid & 31, wid = tid >> 5;
    const int wm = wid >> 1, wn = wid & 1;
    const int bh = blockIdx.y;
    const int s0 = blockIdx.x * 128;
    const size_t base = (size_t)bh * SEQ * DK;
    const unsigned sb = smem_u32(sma);

    #pragma unroll
    for (int u = 0; u < 4; u++) {
        int idx = u * 256 + tid;
        int r = idx >> 3, c = idx & 7;
        size_t g = base + (size_t)(s0 + r) * DK + c * 8;
        *reinterpret_cast<uint4*>(sma + A_QH_B + (r * ALD + c * 8) * 2) =
            *reinterpret_cast<const uint4*>(Qhi + g);
        *reinterpret_cast<uint4*>(sma + A_QL_B + (r * ALD + c * 8) * 2) =
            *reinterpret_cast<const uint4*>(Qlo + g);
    }

    auto issue = [&](int s, int t0) {
        unsigned stg = sb + A_STG_B + s * 36864;
        #pragma unroll
        for (int u = 0; u < 2; u++) {
            int idx = u * 256 + tid;
            int r = idx >> 3, c = idx & 7;
            size_t g = (base + (size_t)(t0 + r) * DK) * 2 + c * 16;
            unsigned d = (unsigned)(r * ALD + c * 8) * 2;
            CPA16(stg + A_KH_B + d, (const char*)Khi + g);
            CPA16(stg + A_KL_B + d, (const char*)Klo + g);
            CPA16(stg + A_VH_B + d, (const char*)Vhi + g);
            CPA16(stg + A_VL_B + d, (const char*)Vlo + g);
        }
    };

    float oacc[2][8][4];
    #pragma unroll
    for (int i = 0; i < 2; i++)
        #pragma unroll
        for (int j = 0; j < 8; j++)
            #pragma unroll
            for (int k = 0; k < 4; k++) oacc[i][j][k] = 0.0f;

    issue(0, 0);
    CP_COMMIT();

    const int NC = SEQ / 64;   // 32
    for (int c = 0; c < NC; c++) {
        const int p = c & 1;
        CP_WAIT0();
        __syncthreads();
        if (c + 1 < NC) { issue(p ^ 1, (c + 1) * 64); CP_COMMIT(); }

        const unsigned stg = sb + A_STG_B + p * 36864;

        float sacc[2][4][4];
        #pragma unroll
        for (int i = 0; i < 2; i++)
            #pragma unroll
            for (int j = 0; j < 4; j++)
                #pragma unroll
                for (int k = 0; k < 4; k++) sacc[i][j][k] = 0.0f;

        #pragma unroll
        for (int ks = 0; ks < 4; ks++) {
            const int kr = ks * 16;
            unsigned ah[2][4], al[2][4], bh_[2][4], bl_[2][4];
            #pragma unroll
            for (int mi = 0; mi < 2; mi++) {
                int m = wm * 32 + mi * 16 + (lane & 15);
                int kk = kr + (lane >> 4) * 8;
                ldsm4(ah[mi][0], ah[mi][1], ah[mi][2], ah[mi][3],
                      sb + A_QH_B + (m * ALD + kk) * 2);
                ldsm4(al[mi][0], al[mi][1], al[mi][2], al[mi][3],
                      sb + A_QL_B + (m * ALD + kk) * 2);
            }
            #pragma unroll
            for (int ni2 = 0; ni2 < 2; ni2++) {
                int n = wn * 32 + ni2 * 16 + (lane >> 4) * 8 + (lane & 7);
                int kk = kr + ((lane >> 3) & 1) * 8;
                ldsm4(bh_[ni2][0], bh_[ni2][1], bh_[ni2][2], bh_[ni2][3],
                      stg + A_KH_B + (n * ALD + kk) * 2);
                ldsm4(bl_[ni2][0], bl_[ni2][1], bl_[ni2][2], bl_[ni2][3],
                      stg + A_KL_B + (n * ALD + kk) * 2);
            }
            #pragma unroll
            for (int mi = 0; mi < 2; mi++)
                #pragma unroll
                for (int ni = 0; ni < 4; ni++) {
                    unsigned* bhp = &bh_[ni >> 1][(ni & 1) * 2];
                    unsigned* blp = &bl_[ni >> 1][(ni & 1) * 2];
                    mma_bf16(sacc[mi][ni], ah[mi], bhp[0], bhp[1]);
                    mma_bf16(sacc[mi][ni], ah[mi], blp[0], blp[1]);
                    mma_bf16(sacc[mi][ni], al[mi], bhp[0], bhp[1]);
                }
        }

        #pragma unroll
        for (int j = 0; j < 2; j++) {
            unsigned sa_h[2][4], sa_l[2][4];
            #pragma unroll
            for (int mi = 0; mi < 2; mi++) {
                float* t0 = sacc[mi][2*j];
                float* t1 = sacc[mi][2*j + 1];
                sa_h[mi][0] = pack_hilo(t0[0]*ATT_SCALE, t0[1]*ATT_SCALE, sa_l[mi][0]);
                sa_h[mi][1] = pack_hilo(t0[2]*ATT_SCALE, t0[3]*ATT_SCALE, sa_l[mi][1]);
                sa_h[mi][2] = pack_hilo(t1[0]*ATT_SCALE, t1[1]*ATT_SCALE, sa_l[mi][2]);
                sa_h[mi][3] = pack_hilo(t1[2]*ATT_SCALE, t1[3]*ATT_SCALE, sa_l[mi][3]);
            }
            int kk = wn * 32 + j * 16 + (lane & 7) + ((lane >> 3) & 1) * 8;
            unsigned vh[4][4], vl[4][4];
            #pragma unroll
            for (int no2 = 0; no2 < 4; no2++) {
                int n = no2 * 16 + (lane >> 4) * 8;
                ldsm4t(vh[no2][0], vh[no2][1], vh[no2][2], vh[no2][3],
                       stg + A_VH_B + (kk * ALD + n) * 2);
                ldsm4t(vl[no2][0], vl[no2][1], vl[no2][2], vl[no2][3],
                       stg + A_VL_B + (kk * ALD + n) * 2);
            }
            #pragma unroll
            for (int mi = 0; mi < 2; mi++)
                #pragma unroll
                for (int no = 0; no < 8; no++) {
                    unsigned* bhp = &vh[no >> 1][(no & 1) * 2];
                    unsigned* blp = &vl[no >> 1][(no & 1) * 2];
                    mma_bf16(oacc[mi][no], sa_h[mi], bhp[0], bhp[1]);
                    mma_bf16(oacc[mi][no], sa_h[mi], blp[0], blp[1]);
                    mma_bf16(oacc[mi][no], sa_l[mi], bhp[0], bhp[1]);
                }
        }
    }

    __syncthreads();
    float* sOb = reinterpret_cast<float*>(sma + A_STG_B) + wn * (128 * OLD);
    #pragma unroll
    for (int mi = 0; mi < 2; mi++)
        #pragma unroll
        for (int no = 0; no < 8; no++) {
            int row = wm * 32 + mi * 16 + (lane >> 2);
            int col = no * 8 + (lane & 3) * 2;
            *reinterpret_cast<float2*>(&sOb[row * OLD + col]) =
                make_float2(oacc[mi][no][0], oacc[mi][no][1]);
            *reinterpret_cast<float2*>(&sOb[(row + 8) * OLD + col]) =
                make_float2(oacc[mi][no][2], oacc[mi][no][3]);
        }
    __syncthreads();

    float* p0buf = reinterpret_cast<float*>(sma + A_STG_B);
    float* p1buf = p0buf + 128 * OLD;
    #pragma unroll
    for (int i = 0; i < 16; i++) {
        int r = wid * 16 + i;
        float v0 = p0buf[r * OLD + lane]      + p1buf[r * OLD + lane];
        float v1 = p0buf[r * OLD + lane + 32] + p1buf[r * OLD + lane + 32];
        float mx = fmaxf(v0, v1);
        #pragma unroll
        for (int o = 16; o > 0; o >>= 1)
            mx = fmaxf(mx, __shfl_xor_sync(0xffffffffu, mx, o));
        float e0 = __expf(v0 - mx), e1 = __expf(v1 - mx);
        float s = e0 + e1;
        #pragma unroll
        for (int o = 16; o > 0; o >>= 1) s += __shfl_xor_sync(0xffffffffu, s, o);
        float inv = 1.0f / s;
        float q0 = e0 * inv, q1 = e1 * inv;
        size_t g = base + (size_t)(s0 + r) * DK;
        bf16 h0 = __float2bfloat16(q0), h1 = __float2bfloat16(q1);
        Mhi[g + lane]      = h0;
        Mhi[g + lane + 32] = h1;
        Mlo[g + lane]      = __float2bfloat16(q0 - __bfloat162float(h0));
        Mlo[g + lane + 32] = __float2bfloat16(q1 - __bfloat162float(h1));
    }
}

// ===========================================================================
// Launch
// ===========================================================================
extern "C" void kernel_launch(void* const* d_in, const int* in_sizes, int n_in,
                              void* d_out, int out_size)
{
    const float* x  = (const float*)d_in[0];
    const float* Wq = (const float*)d_in[1];
    const float* bq = (const float*)d_in[2];
    const float* Wk = (const float*)d_in[3];
    const float* bk = (const float*)d_in[4];
    const float* Wv = (const float*)d_in[5];
    const float* bv = (const float*)d_in[6];
    const float* Wo = (const float*)d_in[7];
    const float* bo = (const float*)d_in[8];
    const float* Wf = (const float*)d_in[9];
    const float* bf_ = (const float*)d_in[10];
    float* out = (float*)d_out;

    bf16 *xhi, *xlo, *Whi, *Wlo, *Qhi, *Qlo, *Khi, *Klo, *Vhi, *Vlo, *Mhi, *Mlo, *Hhi, *Hlo;
    cudaGetSymbolAddress((void**)&xhi, g_xhi); cudaGetSymbolAddress((void**)&xlo, g_xlo);
    cudaGetSymbolAddress((void**)&Whi, g_Whi); cudaGetSymbolAddress((void**)&Wlo, g_Wlo);
    cudaGetSymbolAddress((void**)&Qhi, g_Qhi); cudaGetSymbolAddress((void**)&Qlo, g_Qlo);
    cudaGetSymbolAddress((void**)&Khi, g_Khi); cudaGetSymbolAddress((void**)&Klo, g_Klo);
    cudaGetSymbolAddress((void**)&Vhi, g_Vhi); cudaGetSymbolAddress((void**)&Vlo, g_Vlo);
    cudaGetSymbolAddress((void**)&Mhi, g_Mhi); cudaGetSymbolAddress((void**)&Mlo, g_Mlo);
    cudaGetSymbolAddress((void**)&Hhi, g_Hhi); cudaGetSymbolAddress((void**)&Hlo, g_Hlo);

    cudaFuncSetAttribute(mma_gemm, cudaFuncAttributeMaxDynamicSharedMemorySize, GEMM_SMEM);
    cudaFuncSetAttribute(qkv_gemm, cudaFuncAttributeMaxDynamicSharedMemorySize, GEMM_SMEM);
    cudaFuncSetAttribute(attn_mma, cudaFuncAttributeMaxDynamicSharedMemorySize, ATTN_SMEM);

    int n4tot = N4X + 5 * N4W;
    cvt_all<<<(n4tot + 255)/256, 256>>>(x, Wq, Wk, Wv, Wo, Wf, xhi, xlo, Whi, Wlo);

    dim3 qgrid(DM/128, MROWS/128, 3);   // (6, 32, 3)
    qkv_gemm<<<qgrid, 256, GEMM_SMEM>>>(xhi, xlo, Whi, Wlo, bq, bk, bv,
                                        Qhi, Qlo, Khi, Klo, Vhi, Vlo);

    dim3 agrid(SEQ/128, BD*NH);         // (16, 24)
    attn_mma<<<agrid, 256, ATTN_SMEM>>>(Qhi, Qlo, Khi, Klo, Vhi, Vlo, Mhi, Mlo);

    const int WN = DM * DM;
    dim3 ggrid(DM/128, MROWS/128);      // (6, 32)
    mma_gemm<<<ggrid, 256, GEMM_SMEM>>>(Mhi, Mlo, Whi+3*(size_t)WN, Wlo+3*(size_t)WN, bo, nullptr, Hhi, Hlo);
    mma_gemm<<<ggrid, 256, GEMM_SMEM>>>(Hhi, Hlo, Whi+4*(size_t)WN, Wlo+4*(size_t)WN, bf_, out, nullptr, nullptr);
}

// round 8
// speedup vs baseline: 1.0573x; 1.0573x over previous
#include <cuda_runtime.h>
#include <cuda_bf16.h>

#define BD      2
#define SEQ     2048
#define DM      768
#define NH      12
#define DK      64
#define MROWS   (BD*SEQ)
#define ATT_SCALE 0.125f

typedef __nv_bfloat16 bf16;

// ===========================================================================
// helpers
// ===========================================================================
__device__ __forceinline__ unsigned smem_u32(const void* p) {
    unsigned a;
    asm("{ .reg .u64 t; cvta.to.shared.u64 t, %1; cvt.u32.u64 %0, t; }"
        : "=r"(a) : "l"(p));
    return a;
}
__device__ __forceinline__ void ldsm4(unsigned& r0, unsigned& r1, unsigned& r2,
                                      unsigned& r3, unsigned a) {
    asm volatile("ldmatrix.sync.aligned.m8n8.x4.shared.b16 {%0,%1,%2,%3}, [%4];"
        : "=r"(r0), "=r"(r1), "=r"(r2), "=r"(r3) : "r"(a));
}
__device__ __forceinline__ void ldsm4t(unsigned& r0, unsigned& r1, unsigned& r2,
                                       unsigned& r3, unsigned a) {
    asm volatile("ldmatrix.sync.aligned.m8n8.x4.trans.shared.b16 {%0,%1,%2,%3}, [%4];"
        : "=r"(r0), "=r"(r1), "=r"(r2), "=r"(r3) : "r"(a));
}
__device__ __forceinline__ void mma_bf16(float* c, const unsigned* a,
                                         unsigned b0, unsigned b1) {
    asm volatile("mma.sync.aligned.m16n8k16.row.col.f32.bf16.bf16.f32 "
        "{%0,%1,%2,%3},{%4,%5,%6,%7},{%8,%9},{%0,%1,%2,%3};"
        : "+f"(c[0]), "+f"(c[1]), "+f"(c[2]), "+f"(c[3])
        : "r"(a[0]), "r"(a[1]), "r"(a[2]), "r"(a[3]), "r"(b0), "r"(b1));
}
__device__ __forceinline__ unsigned pack_hilo(float x, float y, unsigned& lo) {
    bf16 hx = __float2bfloat16(x), hy = __float2bfloat16(y);
    bf16 lx = __float2bfloat16(x - __bfloat162float(hx));
    bf16 ly = __float2bfloat16(y - __bfloat162float(hy));
    lo = (unsigned)__bfloat16_as_ushort(lx) | ((unsigned)__bfloat16_as_ushort(ly) << 16);
    return (unsigned)__bfloat16_as_ushort(hx) | ((unsigned)__bfloat16_as_ushort(hy) << 16);
}
#define CPA16(d, s) \
    asm volatile("cp.async.cg.shared.global [%0], [%1], 16;" :: "r"(d), "l"(s) : "memory")
#define CP_COMMIT() asm volatile("cp.async.commit_group;" ::: "memory")
#define CP_WAIT1()  asm volatile("cp.async.wait_group 1;" ::: "memory")
#define CP_WAIT0()  asm volatile("cp.async.wait_group 0;" ::: "memory")

// ===========================================================================
// scratch
// ===========================================================================
__device__ bf16 g_xhi[MROWS*DM], g_xlo[MROWS*DM];
__device__ bf16 g_Whi[5*DM*DM],  g_Wlo[5*DM*DM];
__device__ bf16 g_Qhi[MROWS*DM], g_Qlo[MROWS*DM];
__device__ bf16 g_Khi[MROWS*DM], g_Klo[MROWS*DM];
__device__ bf16 g_Vhi[MROWS*DM], g_Vlo[MROWS*DM];
__device__ bf16 g_Mhi[MROWS*DM], g_Mlo[MROWS*DM];
__device__ bf16 g_Hhi[MROWS*DM], g_Hlo[MROWS*DM];

// ===========================================================================
// merged fp32 -> bf16 hi/lo splitter (one launch)
// ===========================================================================
#define N4X (MROWS*DM/4)
#define N4W (DM*DM/4)
__global__ void __launch_bounds__(256) cvt_all(
    const float* __restrict__ x,
    const float* __restrict__ Wq, const float* __restrict__ Wk,
    const float* __restrict__ Wv, const float* __restrict__ Wo,
    const float* __restrict__ Wf,
    bf16* __restrict__ xhi, bf16* __restrict__ xlo,
    bf16* __restrict__ Whi, bf16* __restrict__ Wlo)
{
    int i = blockIdx.x * blockDim.x + threadIdx.x;
    const float* src; bf16 *hi, *lo; int off;
    if (i < N4X) { src = x; hi = xhi; lo = xlo; off = i; }
    else {
        int j = i - N4X;
        if (j >= 5 * N4W) return;
        int w = j / N4W;
        off = j - w * N4W;
        src = (w == 0) ? Wq : (w == 1) ? Wk : (w == 2) ? Wv : (w == 3) ? Wo : Wf;
        hi = Whi + (size_t)w * (DM*DM);
        lo = Wlo + (size_t)w * (DM*DM);
    }
    float4 v = reinterpret_cast<const float4*>(src)[off];
    uint2 hp, lp;
    hp.x = pack_hilo(v.x, v.y, lp.x);
    hp.y = pack_hilo(v.z, v.w, lp.y);
    reinterpret_cast<uint2*>(hi)[off] = hp;
    reinterpret_cast<uint2*>(lo)[off] = lp;
}

// ===========================================================================
// GEMM (round-6 proven config): C = A @ W^T + bias, split-bf16 3-pass,
// cp.async 2-stage. Tile 128x64, K-chunk 64, 8 warps (4M x 2N), warp 32x32.
// ===========================================================================
#define GLD 72
#define G_AH_B 0
#define G_AL_B 18432
#define G_BH_B 36864
#define G_BL_B 46080
#define G_STAGE_B 55296
#define GEMM_SMEM (2*G_STAGE_B)

__device__ __forceinline__ void gemm_core(
    const bf16* __restrict__ Ahi, const bf16* __restrict__ Alo,
    const bf16* __restrict__ Bhi, const bf16* __restrict__ Blo,
    const float* __restrict__ bias,
    float* __restrict__ Cf, bf16* __restrict__ Chi, bf16* __restrict__ Clo)
{
    extern __shared__ char smc[];
    const int tid = threadIdx.x, lane = tid & 31, wid = tid >> 5;
    const int wm = wid >> 1, wn = wid & 1;
    const int row0 = blockIdx.y * 128, col0 = blockIdx.x * 64;
    const unsigned sb = smem_u32(smc);

    float acc[2][4][4];
    #pragma unroll
    for (int i = 0; i < 2; i++)
        #pragma unroll
        for (int j = 0; j < 4; j++)
            #pragma unroll
            for (int k = 0; k < 4; k++) acc[i][j][k] = 0.0f;

    auto issue = [&](int s, int kc) {
        unsigned stg = sb + s * G_STAGE_B;
        #pragma unroll
        for (int u = 0; u < 4; u++) {
            int idx = u * 256 + tid;
            int r = idx >> 3, c = idx & 7;
            const char* ga = (const char*)(Ahi + (size_t)(row0 + r) * DM + kc) + c * 16;
            const char* gl = (const char*)(Alo + (size_t)(row0 + r) * DM + kc) + c * 16;
            unsigned d = (unsigned)(r * GLD + c * 8) * 2;
            CPA16(stg + G_AH_B + d, ga);
            CPA16(stg + G_AL_B + d, gl);
        }
        #pragma unroll
        for (int u = 0; u < 2; u++) {
            int idx = u * 256 + tid;
            int r = idx >> 3, c = idx & 7;
            const char* gh = (const char*)(Bhi + (size_t)(col0 + r) * DM + kc) + c * 16;
            const char* gl = (const char*)(Blo + (size_t)(col0 + r) * DM + kc) + c * 16;
            unsigned d = (unsigned)(r * GLD + c * 8) * 2;
            CPA16(stg + G_BH_B + d, gh);
            CPA16(stg + G_BL_B + d, gl);
        }
    };

    issue(0, 0);
    CP_COMMIT();

    const int NC = DM / 64;   // 12
    for (int c = 0; c < NC; c++) {
        const int p = c & 1;
        CP_WAIT0();
        __syncthreads();
        if (c + 1 < NC) { issue(p ^ 1, (c + 1) * 64); CP_COMMIT(); }

        const unsigned stg = sb + p * G_STAGE_B;
        #pragma unroll
        for (int ks = 0; ks < 4; ks++) {
            const int kr = ks * 16;
            unsigned ah[2][4], al[2][4], bh[2][4], bl[2][4];
            #pragma unroll
            for (int mi = 0; mi < 2; mi++) {
                int m = wm * 32 + mi * 16 + (lane & 15);
                int kk = kr + (lane >> 4) * 8;
                ldsm4(ah[mi][0], ah[mi][1], ah[mi][2], ah[mi][3],
                      stg + G_AH_B + (m * GLD + kk) * 2);
                ldsm4(al[mi][0], al[mi][1], al[mi][2], al[mi][3],
                      stg + G_AL_B + (m * GLD + kk) * 2);
            }
            #pragma unroll
            for (int ni2 = 0; ni2 < 2; ni2++) {
                int n = wn * 32 + ni2 * 16 + (lane >> 4) * 8 + (lane & 7);
                int kk = kr + ((lane >> 3) & 1) * 8;
                ldsm4(bh[ni2][0], bh[ni2][1], bh[ni2][2], bh[ni2][3],
                      stg + G_BH_B + (n * GLD + kk) * 2);
                ldsm4(bl[ni2][0], bl[ni2][1], bl[ni2][2], bl[ni2][3],
                      stg + G_BL_B + (n * GLD + kk) * 2);
            }
            #pragma unroll
            for (int mi = 0; mi < 2; mi++)
                #pragma unroll
                for (int ni = 0; ni < 4; ni++) {
                    unsigned* bhp = &bh[ni >> 1][(ni & 1) * 2];
                    unsigned* blp = &bl[ni >> 1][(ni & 1) * 2];
                    mma_bf16(acc[mi][ni], ah[mi], bhp[0], bhp[1]);
                    mma_bf16(acc[mi][ni], ah[mi], blp[0], blp[1]);
                    mma_bf16(acc[mi][ni], al[mi], bhp[0], bhp[1]);
                }
        }
    }

    #pragma unroll
    for (int mi = 0; mi < 2; mi++)
        #pragma unroll
        for (int ni = 0; ni < 4; ni++) {
            int row = row0 + wm * 32 + mi * 16 + (lane >> 2);
            int col = col0 + wn * 32 + ni * 8 + (lane & 3) * 2;
            float2 bv = *reinterpret_cast<const float2*>(&bias[col]);
            #pragma unroll
            for (int h = 0; h < 2; h++) {
                int r = row + h * 8;
                float vx = acc[mi][ni][h * 2 + 0] + bv.x;
                float vy = acc[mi][ni][h * 2 + 1] + bv.y;
                size_t off = (size_t)r * DM + col;
                if (Cf) *reinterpret_cast<float2*>(&Cf[off]) = make_float2(vx, vy);
                if (Chi) {
                    unsigned lo, hi = pack_hilo(vx, vy, lo);
                    *reinterpret_cast<unsigned*>(&Chi[off]) = hi;
                    *reinterpret_cast<unsigned*>(&Clo[off]) = lo;
                }
            }
        }
}

__global__ void __launch_bounds__(256, 2) mma_gemm(
    const bf16* __restrict__ Ahi, const bf16* __restrict__ Alo,
    const bf16* __restrict__ Bhi, const bf16* __restrict__ Blo,
    const float* __restrict__ bias,
    float* __restrict__ Cf, bf16* __restrict__ Chi, bf16* __restrict__ Clo)
{
    gemm_core(Ahi, Alo, Bhi, Blo, bias, Cf, Chi, Clo);
}

__global__ void __launch_bounds__(256, 2) qkv_gemm(
    const bf16* __restrict__ xhi, const bf16* __restrict__ xlo,
    const bf16* __restrict__ Whi, const bf16* __restrict__ Wlo,
    const float* __restrict__ bq, const float* __restrict__ bk,
    const float* __restrict__ bv,
    bf16* __restrict__ Qhi, bf16* __restrict__ Qlo,
    bf16* __restrict__ Khi, bf16* __restrict__ Klo,
    bf16* __restrict__ Vhi, bf16* __restrict__ Vlo)
{
    const int z = blockIdx.z;
    const int WN = DM * DM;
    const float* bias = (z == 0) ? bq : (z == 1) ? bk : bv;
    bf16* Chi = (z == 0) ? Qhi : (z == 1) ? Khi : Vhi;
    bf16* Clo = (z == 0) ? Qlo : (z == 1) ? Klo : Vlo;
    gemm_core(xhi, xlo, Whi + (size_t)z * WN, Wlo + (size_t)z * WN, bias,
              nullptr, Chi, Clo);
}

// ===========================================================================
// Attention: 128 Q-rows/block, 8 warps, S register-resident, 3-stage cp.async
// K/V pipeline (wait_group 1 keeps one chunk in flight during compute).
// ===========================================================================
#define ALD 72
#define A_QH_B 0
#define A_QL_B 18432
#define A_STG_B 36864
#define A_STG_SZ 36864
#define A_KH_B 0
#define A_KL_B 9216
#define A_VH_B 18432
#define A_VL_B 27648
#define ATTN_SMEM (36864 + 3*A_STG_SZ)   // 147456
#define OLD 66

__global__ void __launch_bounds__(256) attn_mma(
    const bf16* __restrict__ Qhi, const bf16* __restrict__ Qlo,
    const bf16* __restrict__ Khi, const bf16* __restrict__ Klo,
    const bf16* __restrict__ Vhi, const bf16* __restrict__ Vlo,
    bf16* __restrict__ Mhi, bf16* __restrict__ Mlo)
{
    extern __shared__ char sma[];
    const int tid = threadIdx.x, lane = tid & 31, wid = tid >> 5;
    const int wm = wid >> 1, wn = wid & 1;
    const int bh = blockIdx.y;
    const int s0 = blockIdx.x * 128;
    const size_t base = (size_t)bh * SEQ * DK;
    const unsigned sb = smem_u32(sma);

    #pragma unroll
    for (int u = 0; u < 4; u++) {
        int idx = u * 256 + tid;
        int r = idx >> 3, c = idx & 7;
        size_t g = base + (size_t)(s0 + r) * DK + c * 8;
        *reinterpret_cast<uint4*>(sma + A_QH_B + (r * ALD + c * 8) * 2) =
            *reinterpret_cast<const uint4*>(Qhi + g);
        *reinterpret_cast<uint4*>(sma + A_QL_B + (r * ALD + c * 8) * 2) =
            *reinterpret_cast<const uint4*>(Qlo + g);
    }

    auto issue = [&](int s, int t0) {
        unsigned stg = sb + A_STG_B + s * A_STG_SZ;
        #pragma unroll
        for (int u = 0; u < 2; u++) {
            int idx = u * 256 + tid;
            int r = idx >> 3, c = idx & 7;
            size_t g = (base + (size_t)(t0 + r) * DK) * 2 + c * 16;
            unsigned d = (unsigned)(r * ALD + c * 8) * 2;
            CPA16(stg + A_KH_B + d, (const char*)Khi + g);
            CPA16(stg + A_KL_B + d, (const char*)Klo + g);
            CPA16(stg + A_VH_B + d, (const char*)Vhi + g);
            CPA16(stg + A_VL_B + d, (const char*)Vlo + g);
        }
    };

    float oacc[2][8][4];
    #pragma unroll
    for (int i = 0; i < 2; i++)
        #pragma unroll
        for (int j = 0; j < 8; j++)
            #pragma unroll
            for (int k = 0; k < 4; k++) oacc[i][j][k] = 0.0f;

    issue(0, 0);
    CP_COMMIT();
    issue(1, 64);
    CP_COMMIT();

    const int NC = SEQ / 64;   // 32
    int p = 0;
    for (int c = 0; c < NC; c++) {
        if (c + 1 < NC) { CP_WAIT1(); }   // stage p arrived, next may fly
        else            { CP_WAIT0(); }
        __syncthreads();                   // all warps done with stage being refilled
        if (c + 2 < NC) { issue((p + 2) % 3, (c + 2) * 64); CP_COMMIT(); }

        const unsigned stg = sb + A_STG_B + p * A_STG_SZ;

        float sacc[2][4][4];
        #pragma unroll
        for (int i = 0; i < 2; i++)
            #pragma unroll
            for (int j = 0; j < 4; j++)
                #pragma unroll
                for (int k = 0; k < 4; k++) sacc[i][j][k] = 0.0f;

        #pragma unroll
        for (int ks = 0; ks < 4; ks++) {
            const int kr = ks * 16;
            unsigned ah[2][4], al[2][4], bh_[2][4], bl_[2][4];
            #pragma unroll
            for (int mi = 0; mi < 2; mi++) {
                int m = wm * 32 + mi * 16 + (lane & 15);
                int kk = kr + (lane >> 4) * 8;
                ldsm4(ah[mi][0], ah[mi][1], ah[mi][2], ah[mi][3],
                      sb + A_QH_B + (m * ALD + kk) * 2);
                ldsm4(al[mi][0], al[mi][1], al[mi][2], al[mi][3],
                      sb + A_QL_B + (m * ALD + kk) * 2);
            }
            #pragma unroll
            for (int ni2 = 0; ni2 < 2; ni2++) {
                int n = wn * 32 + ni2 * 16 + (lane >> 4) * 8 + (lane & 7);
                int kk = kr + ((lane >> 3) & 1) * 8;
                ldsm4(bh_[ni2][0], bh_[ni2][1], bh_[ni2][2], bh_[ni2][3],
                      stg + A_KH_B + (n * ALD + kk) * 2);
                ldsm4(bl_[ni2][0], bl_[ni2][1], bl_[ni2][2], bl_[ni2][3],
                      stg + A_KL_B + (n * ALD + kk) * 2);
            }
            #pragma unroll
            for (int mi = 0; mi < 2; mi++)
                #pragma unroll
                for (int ni = 0; ni < 4; ni++) {
                    unsigned* bhp = &bh_[ni >> 1][(ni & 1) * 2];
                    unsigned* blp = &bl_[ni >> 1][(ni & 1) * 2];
                    mma_bf16(sacc[mi][ni], ah[mi], bhp[0], bhp[1]);
                    mma_bf16(sacc[mi][ni], ah[mi], blp[0], blp[1]);
                    mma_bf16(sacc[mi][ni], al[mi], bhp[0], bhp[1]);
                }
        }

        #pragma unroll
        for (int j = 0; j < 2; j++) {
            unsigned sa_h[2][4], sa_l[2][4];
            #pragma unroll
            for (int mi = 0; mi < 2; mi++) {
                float* t0 = sacc[mi][2*j];
                float* t1 = sacc[mi][2*j + 1];
                sa_h[mi][0] = pack_hilo(t0[0]*ATT_SCALE, t0[1]*ATT_SCALE, sa_l[mi][0]);
                sa_h[mi][1] = pack_hilo(t0[2]*ATT_SCALE, t0[3]*ATT_SCALE, sa_l[mi][1]);
                sa_h[mi][2] = pack_hilo(t1[0]*ATT_SCALE, t1[1]*ATT_SCALE, sa_l[mi][2]);
                sa_h[mi][3] = pack_hilo(t1[2]*ATT_SCALE, t1[3]*ATT_SCALE, sa_l[mi][3]);
            }
            int kk = wn * 32 + j * 16 + (lane & 7) + ((lane >> 3) & 1) * 8;
            unsigned vh[4][4], vl[4][4];
            #pragma unroll
            for (int no2 = 0; no2 < 4; no2++) {
                int n = no2 * 16 + (lane >> 4) * 8;
                ldsm4t(vh[no2][0], vh[no2][1], vh[no2][2], vh[no2][3],
                       stg + A_VH_B + (kk * ALD + n) * 2);
                ldsm4t(vl[no2][0], vl[no2][1], vl[no2][2], vl[no2][3],
                       stg + A_VL_B + (kk * ALD + n) * 2);
            }
            #pragma unroll
            for (int mi = 0; mi < 2; mi++)
                #pragma unroll
                for (int no = 0; no < 8; no++) {
                    unsigned* bhp = &vh[no >> 1][(no & 1) * 2];
                    unsigned* blp = &vl[no >> 1][(no & 1) * 2];
                    mma_bf16(oacc[mi][no], sa_h[mi], bhp[0], bhp[1]);
                    mma_bf16(oacc[mi][no], sa_h[mi], blp[0], blp[1]);
                    mma_bf16(oacc[mi][no], sa_l[mi], bhp[0], bhp[1]);
                }
        }
        p = (p + 1) % 3;
    }

    __syncthreads();
    float* sOb = reinterpret_cast<float*>(sma + A_STG_B) + wn * (128 * OLD);
    #pragma unroll
    for (int mi = 0; mi < 2; mi++)
        #pragma unroll
        for (int no = 0; no < 8; no++) {
            int row = wm * 32 + mi * 16 + (lane >> 2);
            int col = no * 8 + (lane & 3) * 2;
            *reinterpret_cast<float2*>(&sOb[row * OLD + col]) =
                make_float2(oacc[mi][no][0], oacc[mi][no][1]);
            *reinterpret_cast<float2*>(&sOb[(row + 8) * OLD + col]) =
                make_float2(oacc[mi][no][2], oacc[mi][no][3]);
        }
    __syncthreads();

    float* p0buf = reinterpret_cast<float*>(sma + A_STG_B);
    float* p1buf = p0buf + 128 * OLD;
    #pragma unroll
    for (int i = 0; i < 16; i++) {
        int r = wid * 16 + i;
        float v0 = p0buf[r * OLD + lane]      + p1buf[r * OLD + lane];
        float v1 = p0buf[r * OLD + lane + 32] + p1buf[r * OLD + lane + 32];
        float mx = fmaxf(v0, v1);
        #pragma unroll
        for (int o = 16; o > 0; o >>= 1)
            mx = fmaxf(mx, __shfl_xor_sync(0xffffffffu, mx, o));
        float e0 = __expf(v0 - mx), e1 = __expf(v1 - mx);
        float s = e0 + e1;
        #pragma unroll
        for (int o = 16; o > 0; o >>= 1) s += __shfl_xor_sync(0xffffffffu, s, o);
        float inv = 1.0f / s;
        float q0 = e0 * inv, q1 = e1 * inv;
        size_t g = base + (size_t)(s0 + r) * DK;
        bf16 h0 = __float2bfloat16(q0), h1 = __float2bfloat16(q1);
        Mhi[g + lane]      = h0;
        Mhi[g + lane + 32] = h1;
        Mlo[g + lane]      = __float2bfloat16(q0 - __bfloat162float(h0));
        Mlo[g + lane + 32] = __float2bfloat16(q1 - __bfloat162float(h1));
    }
}

// ===========================================================================
// Launch
// ===========================================================================
extern "C" void kernel_launch(void* const* d_in, const int* in_sizes, int n_in,
                              void* d_out, int out_size)
{
    const float* x  = (const float*)d_in[0];
    const float* Wq = (const float*)d_in[1];
    const float* bq = (const float*)d_in[2];
    const float* Wk = (const float*)d_in[3];
    const float* bk = (const float*)d_in[4];
    const float* Wv = (const float*)d_in[5];
    const float* bv = (const float*)d_in[6];
    const float* Wo = (const float*)d_in[7];
    const float* bo = (const float*)d_in[8];
    const float* Wf = (const float*)d_in[9];
    const float* bf_ = (const float*)d_in[10];
    float* out = (float*)d_out;

    bf16 *xhi, *xlo, *Whi, *Wlo, *Qhi, *Qlo, *Khi, *Klo, *Vhi, *Vlo, *Mhi, *Mlo, *Hhi, *Hlo;
    cudaGetSymbolAddress((void**)&xhi, g_xhi); cudaGetSymbolAddress((void**)&xlo, g_xlo);
    cudaGetSymbolAddress((void**)&Whi, g_Whi); cudaGetSymbolAddress((void**)&Wlo, g_Wlo);
    cudaGetSymbolAddress((void**)&Qhi, g_Qhi); cudaGetSymbolAddress((void**)&Qlo, g_Qlo);
    cudaGetSymbolAddress((void**)&Khi, g_Khi); cudaGetSymbolAddress((void**)&Klo, g_Klo);
    cudaGetSymbolAddress((void**)&Vhi, g_Vhi); cudaGetSymbolAddress((void**)&Vlo, g_Vlo);
    cudaGetSymbolAddress((void**)&Mhi, g_Mhi); cudaGetSymbolAddress((void**)&Mlo, g_Mlo);
    cudaGetSymbolAddress((void**)&Hhi, g_Hhi); cudaGetSymbolAddress((void**)&Hlo, g_Hlo);

    cudaFuncSetAttribute(mma_gemm, cudaFuncAttributeMaxDynamicSharedMemorySize, GEMM_SMEM);
    cudaFuncSetAttribute(qkv_gemm, cudaFuncAttributeMaxDynamicSharedMemorySize, GEMM_SMEM);
    cudaFuncSetAttribute(attn_mma, cudaFuncAttributeMaxDynamicSharedMemorySize, ATTN_SMEM);

    int n4tot = N4X + 5 * N4W;
    cvt_all<<<(n4tot + 255)/256, 256>>>(x, Wq, Wk, Wv, Wo, Wf, xhi, xlo, Whi, Wlo);

    dim3 qgrid(DM/64, MROWS/128, 3);   // (12, 32, 3)
    qkv_gemm<<<qgrid, 256, GEMM_SMEM>>>(xhi, xlo, Whi, Wlo, bq, bk, bv,
                                        Qhi, Qlo, Khi, Klo, Vhi, Vlo);

    dim3 agrid(SEQ/128, BD*NH);        // (16, 24)
    attn_mma<<<agrid, 256, ATTN_SMEM>>>(Qhi, Qlo, Khi, Klo, Vhi, Vlo, Mhi, Mlo);

    const int WN = DM * DM;
    dim3 ggrid(DM/64, MROWS/128);      // (12, 32)
    mma_gemm<<<ggrid, 256, GEMM_SMEM>>>(Mhi, Mlo, Whi+3*(size_t)WN, Wlo+3*(size_t)WN, bo, nullptr, Hhi, Hlo);
    mma_gemm<<<ggrid, 256, GEMM_SMEM>>>(Hhi, Hlo, Whi+4*(size_t)WN, Wlo+4*(size_t)WN, bf_, out, nullptr, nullptr);
}

// round 9
// speedup vs baseline: 1.1174x; 1.0569x over previous
#include <cuda_runtime.h>
#include <cuda_bf16.h>

#define BD      2
#define SEQ     2048
#define DM      768
#define NH      12
#define DK      64
#define MROWS   (BD*SEQ)
#define ATT_SCALE 0.125f

typedef __nv_bfloat16 bf16;

// ===========================================================================
// helpers
// ===========================================================================
__device__ __forceinline__ unsigned smem_u32(const void* p) {
    unsigned a;
    asm("{ .reg .u64 t; cvta.to.shared.u64 t, %1; cvt.u32.u64 %0, t; }"
        : "=r"(a) : "l"(p));
    return a;
}
__device__ __forceinline__ void ldsm4(unsigned& r0, unsigned& r1, unsigned& r2,
                                      unsigned& r3, unsigned a) {
    asm volatile("ldmatrix.sync.aligned.m8n8.x4.shared.b16 {%0,%1,%2,%3}, [%4];"
        : "=r"(r0), "=r"(r1), "=r"(r2), "=r"(r3) : "r"(a));
}
__device__ __forceinline__ void ldsm4t(unsigned& r0, unsigned& r1, unsigned& r2,
                                       unsigned& r3, unsigned a) {
    asm volatile("ldmatrix.sync.aligned.m8n8.x4.trans.shared.b16 {%0,%1,%2,%3}, [%4];"
        : "=r"(r0), "=r"(r1), "=r"(r2), "=r"(r3) : "r"(a));
}
__device__ __forceinline__ void mma_bf16(float* c, const unsigned* a,
                                         unsigned b0, unsigned b1) {
    asm volatile("mma.sync.aligned.m16n8k16.row.col.f32.bf16.bf16.f32 "
        "{%0,%1,%2,%3},{%4,%5,%6,%7},{%8,%9},{%0,%1,%2,%3};"
        : "+f"(c[0]), "+f"(c[1]), "+f"(c[2]), "+f"(c[3])
        : "r"(a[0]), "r"(a[1]), "r"(a[2]), "r"(a[3]), "r"(b0), "r"(b1));
}
__device__ __forceinline__ unsigned pack_hilo(float x, float y, unsigned& lo) {
    bf16 hx = __float2bfloat16(x), hy = __float2bfloat16(y);
    bf16 lx = __float2bfloat16(x - __bfloat162float(hx));
    bf16 ly = __float2bfloat16(y - __bfloat162float(hy));
    lo = (unsigned)__bfloat16_as_ushort(lx) | ((unsigned)__bfloat16_as_ushort(ly) << 16);
    return (unsigned)__bfloat16_as_ushort(hx) | ((unsigned)__bfloat16_as_ushort(hy) << 16);
}
#define CPA16(d, s) \
    asm volatile("cp.async.cg.shared.global [%0], [%1], 16;" :: "r"(d), "l"(s) : "memory")
#define CP_COMMIT() asm volatile("cp.async.commit_group;" ::: "memory")
#define CP_WAIT1()  asm volatile("cp.async.wait_group 1;" ::: "memory")
#define CP_WAIT0()  asm volatile("cp.async.wait_group 0;" ::: "memory")

// ===========================================================================
// scratch
// ===========================================================================
__device__ bf16 g_xhi[MROWS*DM], g_xlo[MROWS*DM];
__device__ bf16 g_Whi[4*DM*DM],  g_Wlo[4*DM*DM];     // Wq, Wk, Wv, Wf
__device__ bf16 g_WoThi[DM*DM],  g_WoTlo[DM*DM];     // Wo transposed
__device__ bf16 g_Wchi[DM*DM],   g_Wclo[DM*DM];      // Wc = Wf @ Wo
__device__ bf16 g_Qhi[MROWS*DM], g_Qlo[MROWS*DM];
__device__ bf16 g_Khi[MROWS*DM], g_Klo[MROWS*DM];
__device__ bf16 g_Vhi[MROWS*DM], g_Vlo[MROWS*DM];
__device__ bf16 g_Mhi[MROWS*DM], g_Mlo[MROWS*DM];
__device__ float g_bp[DM];                           // b' = Wf@bo + bf
__device__ float g_zb[DM];                           // zero bias

// ===========================================================================
// merged fp32 -> bf16 hi/lo splitter: x + Wq,Wk,Wv,Wf (one launch)
// ===========================================================================
#define N4X (MROWS*DM/4)
#define N4W (DM*DM/4)
__global__ void __launch_bounds__(256) cvt_all(
    const float* __restrict__ x,
    const float* __restrict__ Wq, const float* __restrict__ Wk,
    const float* __restrict__ Wv, const float* __restrict__ Wf,
    bf16* __restrict__ xhi, bf16* __restrict__ xlo,
    bf16* __restrict__ Whi, bf16* __restrict__ Wlo)
{
    int i = blockIdx.x * blockDim.x + threadIdx.x;
    const float* src; bf16 *hi, *lo; int off;
    if (i < N4X) { src = x; hi = xhi; lo = xlo; off = i; }
    else {
        int j = i - N4X;
        if (j >= 4 * N4W) return;
        int w = j / N4W;
        off = j - w * N4W;
        src = (w == 0) ? Wq : (w == 1) ? Wk : (w == 2) ? Wv : Wf;
        hi = Whi + (size_t)w * (DM*DM);
        lo = Wlo + (size_t)w * (DM*DM);
    }
    float4 v = reinterpret_cast<const float4*>(src)[off];
    uint2 hp, lp;
    hp.x = pack_hilo(v.x, v.y, lp.x);
    hp.y = pack_hilo(v.z, v.w, lp.y);
    reinterpret_cast<uint2*>(hi)[off] = hp;
    reinterpret_cast<uint2*>(lo)[off] = lp;
}

// ===========================================================================
// Wo transpose + split: WoT[n,k] = Wo[k,n], emitted as bf16 hi/lo
// ===========================================================================
__global__ void __launch_bounds__(256) trans_wo(
    const float* __restrict__ Wo, bf16* __restrict__ hi, bf16* __restrict__ lo)
{
    __shared__ float t[32][33];
    int bx = blockIdx.x * 32, by = blockIdx.y * 32;
    int tx = threadIdx.x & 31, ty = threadIdx.x >> 5;   // 32x8
    #pragma unroll
    for (int i = 0; i < 32; i += 8)
        t[ty + i][tx] = Wo[(size_t)(by + ty + i) * DM + bx + tx];
    __syncthreads();
    #pragma unroll
    for (int i = 0; i < 32; i += 8) {
        float v = t[tx][ty + i];                 // Wo[by+tx][bx+ty+i]
        bf16 h = __float2bfloat16(v);
        bf16 l = __float2bfloat16(v - __bfloat162float(h));
        size_t o = (size_t)(bx + ty + i) * DM + by + tx;   // WoT[bx+ty+i][by+tx]
        hi[o] = h;
        lo[o] = l;
    }
}

// ===========================================================================
// b' = Wf @ bo + bf  (one warp per output element)
// ===========================================================================
__global__ void __launch_bounds__(256) bprime_k(
    const float* __restrict__ Wf, const float* __restrict__ bo,
    const float* __restrict__ bfv, float* __restrict__ bp)
{
    int n = blockIdx.x * 8 + (threadIdx.x >> 5);
    int lane = threadIdx.x & 31;
    if (n >= DM) return;
    float s = 0.0f;
    for (int j = lane; j < DM; j += 32) s += Wf[(size_t)n * DM + j] * bo[j];
    #pragma unroll
    for (int o = 16; o > 0; o >>= 1) s += __shfl_xor_sync(0xffffffffu, s, o);
    if (lane == 0) bp[n] = s + bfv[n];
}

// ===========================================================================
// GEMM (round-6 proven config): C[M,768] = A @ W^T + bias, split-bf16 3-pass,
// cp.async 2-stage. Tile 128x64, K-chunk 64, 8 warps (4M x 2N), warp 32x32.
// ===========================================================================
#define GLD 72
#define G_AH_B 0
#define G_AL_B 18432
#define G_BH_B 36864
#define G_BL_B 46080
#define G_STAGE_B 55296
#define GEMM_SMEM (2*G_STAGE_B)

__device__ __forceinline__ void gemm_core(
    const bf16* __restrict__ Ahi, const bf16* __restrict__ Alo,
    const bf16* __restrict__ Bhi, const bf16* __restrict__ Blo,
    const float* __restrict__ bias,
    float* __restrict__ Cf, bf16* __restrict__ Chi, bf16* __restrict__ Clo)
{
    extern __shared__ char smc[];
    const int tid = threadIdx.x, lane = tid & 31, wid = tid >> 5;
    const int wm = wid >> 1, wn = wid & 1;
    const int row0 = blockIdx.y * 128, col0 = blockIdx.x * 64;
    const unsigned sb = smem_u32(smc);

    float acc[2][4][4];
    #pragma unroll
    for (int i = 0; i < 2; i++)
        #pragma unroll
        for (int j = 0; j < 4; j++)
            #pragma unroll
            for (int k = 0; k < 4; k++) acc[i][j][k] = 0.0f;

    auto issue = [&](int s, int kc) {
        unsigned stg = sb + s * G_STAGE_B;
        #pragma unroll
        for (int u = 0; u < 4; u++) {
            int idx = u * 256 + tid;
            int r = idx >> 3, c = idx & 7;
            const char* ga = (const char*)(Ahi + (size_t)(row0 + r) * DM + kc) + c * 16;
            const char* gl = (const char*)(Alo + (size_t)(row0 + r) * DM + kc) + c * 16;
            unsigned d = (unsigned)(r * GLD + c * 8) * 2;
            CPA16(stg + G_AH_B + d, ga);
            CPA16(stg + G_AL_B + d, gl);
        }
        #pragma unroll
        for (int u = 0; u < 2; u++) {
            int idx = u * 256 + tid;
            int r = idx >> 3, c = idx & 7;
            const char* gh = (const char*)(Bhi + (size_t)(col0 + r) * DM + kc) + c * 16;
            const char* gl = (const char*)(Blo + (size_t)(col0 + r) * DM + kc) + c * 16;
            unsigned d = (unsigned)(r * GLD + c * 8) * 2;
            CPA16(stg + G_BH_B + d, gh);
            CPA16(stg + G_BL_B + d, gl);
        }
    };

    issue(0, 0);
    CP_COMMIT();

    const int NC = DM / 64;   // 12
    for (int c = 0; c < NC; c++) {
        const int p = c & 1;
        CP_WAIT0();
        __syncthreads();
        if (c + 1 < NC) { issue(p ^ 1, (c + 1) * 64); CP_COMMIT(); }

        const unsigned stg = sb + p * G_STAGE_B;
        #pragma unroll
        for (int ks = 0; ks < 4; ks++) {
            const int kr = ks * 16;
            unsigned ah[2][4], al[2][4], bh[2][4], bl[2][4];
            #pragma unroll
            for (int mi = 0; mi < 2; mi++) {
                int m = wm * 32 + mi * 16 + (lane & 15);
                int kk = kr + (lane >> 4) * 8;
                ldsm4(ah[mi][0], ah[mi][1], ah[mi][2], ah[mi][3],
                      stg + G_AH_B + (m * GLD + kk) * 2);
                ldsm4(al[mi][0], al[mi][1], al[mi][2], al[mi][3],
                      stg + G_AL_B + (m * GLD + kk) * 2);
            }
            #pragma unroll
            for (int ni2 = 0; ni2 < 2; ni2++) {
                int n = wn * 32 + ni2 * 16 + (lane >> 4) * 8 + (lane & 7);
                int kk = kr + ((lane >> 3) & 1) * 8;
                ldsm4(bh[ni2][0], bh[ni2][1], bh[ni2][2], bh[ni2][3],
                      stg + G_BH_B + (n * GLD + kk) * 2);
                ldsm4(bl[ni2][0], bl[ni2][1], bl[ni2][2], bl[ni2][3],
                      stg + G_BL_B + (n * GLD + kk) * 2);
            }
            #pragma unroll
            for (int mi = 0; mi < 2; mi++)
                #pragma unroll
                for (int ni = 0; ni < 4; ni++) {
                    unsigned* bhp = &bh[ni >> 1][(ni & 1) * 2];
                    unsigned* blp = &bl[ni >> 1][(ni & 1) * 2];
                    mma_bf16(acc[mi][ni], ah[mi], bhp[0], bhp[1]);
                    mma_bf16(acc[mi][ni], ah[mi], blp[0], blp[1]);
                    mma_bf16(acc[mi][ni], al[mi], bhp[0], bhp[1]);
                }
        }
    }

    #pragma unroll
    for (int mi = 0; mi < 2; mi++)
        #pragma unroll
        for (int ni = 0; ni < 4; ni++) {
            int row = row0 + wm * 32 + mi * 16 + (lane >> 2);
            int col = col0 + wn * 32 + ni * 8 + (lane & 3) * 2;
            float2 bv = *reinterpret_cast<const float2*>(&bias[col]);
            #pragma unroll
            for (int h = 0; h < 2; h++) {
                int r = row + h * 8;
                float vx = acc[mi][ni][h * 2 + 0] + bv.x;
                float vy = acc[mi][ni][h * 2 + 1] + bv.y;
                size_t off = (size_t)r * DM + col;
                if (Cf) *reinterpret_cast<float2*>(&Cf[off]) = make_float2(vx, vy);
                if (Chi) {
                    unsigned lo, hi = pack_hilo(vx, vy, lo);
                    *reinterpret_cast<unsigned*>(&Chi[off]) = hi;
                    *reinterpret_cast<unsigned*>(&Clo[off]) = lo;
                }
            }
        }
}

__global__ void __launch_bounds__(256, 2) mma_gemm(
    const bf16* __restrict__ Ahi, const bf16* __restrict__ Alo,
    const bf16* __restrict__ Bhi, const bf16* __restrict__ Blo,
    const float* __restrict__ bias,
    float* __restrict__ Cf, bf16* __restrict__ Chi, bf16* __restrict__ Clo)
{
    gemm_core(Ahi, Alo, Bhi, Blo, bias, Cf, Chi, Clo);
}

__global__ void __launch_bounds__(256, 2) qkv_gemm(
    const bf16* __restrict__ xhi, const bf16* __restrict__ xlo,
    const bf16* __restrict__ Whi, const bf16* __restrict__ Wlo,
    const float* __restrict__ bq, const float* __restrict__ bk,
    const float* __restrict__ bv,
    bf16* __restrict__ Qhi, bf16* __restrict__ Qlo,
    bf16* __restrict__ Khi, bf16* __restrict__ Klo,
    bf16* __restrict__ Vhi, bf16* __restrict__ Vlo)
{
    const int z = blockIdx.z;
    const int WN = DM * DM;
    const float* bias = (z == 0) ? bq : (z == 1) ? bk : bv;
    bf16* Chi = (z == 0) ? Qhi : (z == 1) ? Khi : Vhi;
    bf16* Clo = (z == 0) ? Qlo : (z == 1) ? Klo : Vlo;
    gemm_core(xhi, xlo, Whi + (size_t)z * WN, Wlo + (size_t)z * WN, bias,
              nullptr, Chi, Clo);
}

// ===========================================================================
// Attention: 128 Q-rows/block, 8 warps, S register-resident, 3-stage cp.async
// K/V pipeline. (round-8 config)
// ===========================================================================
#define ALD 72
#define A_QH_B 0
#define A_QL_B 18432
#define A_STG_B 36864
#define A_STG_SZ 36864
#define A_KH_B 0
#define A_KL_B 9216
#define A_VH_B 18432
#define A_VL_B 27648
#define ATTN_SMEM (36864 + 3*A_STG_SZ)   // 147456
#define OLD 66

__global__ void __launch_bounds__(256) attn_mma(
    const bf16* __restrict__ Qhi, const bf16* __restrict__ Qlo,
    const bf16* __restrict__ Khi, const bf16* __restrict__ Klo,
    const bf16* __restrict__ Vhi, const bf16* __restrict__ Vlo,
    bf16* __restrict__ Mhi, bf16* __restrict__ Mlo)
{
    extern __shared__ char sma[];
    const int tid = threadIdx.x, lane = tid & 31, wid = tid >> 5;
    const int wm = wid >> 1, wn = wid & 1;
    const int bh = blockIdx.y;
    const int s0 = blockIdx.x * 128;
    const size_t base = (size_t)bh * SEQ * DK;
    const unsigned sb = smem_u32(sma);

    #pragma unroll
    for (int u = 0; u < 4; u++) {
        int idx = u * 256 + tid;
        int r = idx >> 3, c = idx & 7;
        size_t g = base + (size_t)(s0 + r) * DK + c * 8;
        *reinterpret_cast<uint4*>(sma + A_QH_B + (r * ALD + c * 8) * 2) =
            *reinterpret_cast<const uint4*>(Qhi + g);
        *reinterpret_cast<uint4*>(sma + A_QL_B + (r * ALD + c * 8) * 2) =
            *reinterpret_cast<const uint4*>(Qlo + g);
    }

    auto issue = [&](int s, int t0) {
        unsigned stg = sb + A_STG_B + s * A_STG_SZ;
        #pragma unroll
        for (int u = 0; u < 2; u++) {
            int idx = u * 256 + tid;
            int r = idx >> 3, c = idx & 7;
            size_t g = (base + (size_t)(t0 + r) * DK) * 2 + c * 16;
            unsigned d = (unsigned)(r * ALD + c * 8) * 2;
            CPA16(stg + A_KH_B + d, (const char*)Khi + g);
            CPA16(stg + A_KL_B + d, (const char*)Klo + g);
            CPA16(stg + A_VH_B + d, (const char*)Vhi + g);
            CPA16(stg + A_VL_B + d, (const char*)Vlo + g);
        }
    };

    float oacc[2][8][4];
    #pragma unroll
    for (int i = 0; i < 2; i++)
        #pragma unroll
        for (int j = 0; j < 8; j++)
            #pragma unroll
            for (int k = 0; k < 4; k++) oacc[i][j][k] = 0.0f;

    issue(0, 0);
    CP_COMMIT();
    issue(1, 64);
    CP_COMMIT();

    const int NC = SEQ / 64;   // 32
    int p = 0;
    for (int c = 0; c < NC; c++) {
        if (c + 1 < NC) { CP_WAIT1(); }
        else            { CP_WAIT0(); }
        __syncthreads();
        if (c + 2 < NC) { issue((p + 2) % 3, (c + 2) * 64); CP_COMMIT(); }

        const unsigned stg = sb + A_STG_B + p * A_STG_SZ;

        float sacc[2][4][4];
        #pragma unroll
        for (int i = 0; i < 2; i++)
            #pragma unroll
            for (int j = 0; j < 4; j++)
                #pragma unroll
                for (int k = 0; k < 4; k++) sacc[i][j][k] = 0.0f;

        #pragma unroll
        for (int ks = 0; ks < 4; ks++) {
            const int kr = ks * 16;
            unsigned ah[2][4], al[2][4], bh_[2][4], bl_[2][4];
            #pragma unroll
            for (int mi = 0; mi < 2; mi++) {
                int m = wm * 32 + mi * 16 + (lane & 15);
                int kk = kr + (lane >> 4) * 8;
                ldsm4(ah[mi][0], ah[mi][1], ah[mi][2], ah[mi][3],
                      sb + A_QH_B + (m * ALD + kk) * 2);
                ldsm4(al[mi][0], al[mi][1], al[mi][2], al[mi][3],
                      sb + A_QL_B + (m * ALD + kk) * 2);
            }
            #pragma unroll
            for (int ni2 = 0; ni2 < 2; ni2++) {
                int n = wn * 32 + ni2 * 16 + (lane >> 4) * 8 + (lane & 7);
                int kk = kr + ((lane >> 3) & 1) * 8;
                ldsm4(bh_[ni2][0], bh_[ni2][1], bh_[ni2][2], bh_[ni2][3],
                      stg + A_KH_B + (n * ALD + kk) * 2);
                ldsm4(bl_[ni2][0], bl_[ni2][1], bl_[ni2][2], bl_[ni2][3],
                      stg + A_KL_B + (n * ALD + kk) * 2);
            }
            #pragma unroll
            for (int mi = 0; mi < 2; mi++)
                #pragma unroll
                for (int ni = 0; ni < 4; ni++) {
                    unsigned* bhp = &bh_[ni >> 1][(ni & 1) * 2];
                    unsigned* blp = &bl_[ni >> 1][(ni & 1) * 2];
                    mma_bf16(sacc[mi][ni], ah[mi], bhp[0], bhp[1]);
                    mma_bf16(sacc[mi][ni], ah[mi], blp[0], blp[1]);
                    mma_bf16(sacc[mi][ni], al[mi], bhp[0], bhp[1]);
                }
        }

        #pragma unroll
        for (int j = 0; j < 2; j++) {
            unsigned sa_h[2][4], sa_l[2][4];
            #pragma unroll
            for (int mi = 0; mi < 2; mi++) {
                float* t0 = sacc[mi][2*j];
                float* t1 = sacc[mi][2*j + 1];
                sa_h[mi][0] = pack_hilo(t0[0]*ATT_SCALE, t0[1]*ATT_SCALE, sa_l[mi][0]);
                sa_h[mi][1] = pack_hilo(t0[2]*ATT_SCALE, t0[3]*ATT_SCALE, sa_l[mi][1]);
                sa_h[mi][2] = pack_hilo(t1[0]*ATT_SCALE, t1[1]*ATT_SCALE, sa_l[mi][2]);
                sa_h[mi][3] = pack_hilo(t1[2]*ATT_SCALE, t1[3]*ATT_SCALE, sa_l[mi][3]);
            }
            int kk = wn * 32 + j * 16 + (lane & 7) + ((lane >> 3) & 1) * 8;
            unsigned vh[4][4], vl[4][4];
            #pragma unroll
            for (int no2 = 0; no2 < 4; no2++) {
                int n = no2 * 16 + (lane >> 4) * 8;
                ldsm4t(vh[no2][0], vh[no2][1], vh[no2][2], vh[no2][3],
                       stg + A_VH_B + (kk * ALD + n) * 2);
                ldsm4t(vl[no2][0], vl[no2][1], vl[no2][2], vl[no2][3],
                       stg + A_VL_B + (kk * ALD + n) * 2);
            }
            #pragma unroll
            for (int mi = 0; mi < 2; mi++)
                #pragma unroll
                for (int no = 0; no < 8; no++) {
                    unsigned* bhp = &vh[no >> 1][(no & 1) * 2];
                    unsigned* blp = &vl[no >> 1][(no & 1) * 2];
                    mma_bf16(oacc[mi][no], sa_h[mi], bhp[0], bhp[1]);
                    mma_bf16(oacc[mi][no], sa_h[mi], blp[0], blp[1]);
                    mma_bf16(oacc[mi][no], sa_l[mi], bhp[0], bhp[1]);
                }
        }
        p = (p + 1) % 3;
    }

    __syncthreads();
    float* sOb = reinterpret_cast<float*>(sma + A_STG_B) + wn * (128 * OLD);
    #pragma unroll
    for (int mi = 0; mi < 2; mi++)
        #pragma unroll
        for (int no = 0; no < 8; no++) {
            int row = wm * 32 + mi * 16 + (lane >> 2);
            int col = no * 8 + (lane & 3) * 2;
            *reinterpret_cast<float2*>(&sOb[row * OLD + col]) =
                make_float2(oacc[mi][no][0], oacc[mi][no][1]);
            *reinterpret_cast<float2*>(&sOb[(row + 8) * OLD + col]) =
                make_float2(oacc[mi][no][2], oacc[mi][no][3]);
        }
    __syncthreads();

    float* p0buf = reinterpret_cast<float*>(sma + A_STG_B);
    float* p1buf = p0buf + 128 * OLD;
    #pragma unroll
    for (int i = 0; i < 16; i++) {
        int r = wid * 16 + i;
        float v0 = p0buf[r * OLD + lane]      + p1buf[r * OLD + lane];
        float v1 = p0buf[r * OLD + lane + 32] + p1buf[r * OLD + lane + 32];
        float mx = fmaxf(v0, v1);
        #pragma unroll
        for (int o = 16; o > 0; o >>= 1)
            mx = fmaxf(mx, __shfl_xor_sync(0xffffffffu, mx, o));
        float e0 = __expf(v0 - mx), e1 = __expf(v1 - mx);
        float s = e0 + e1;
        #pragma unroll
        for (int o = 16; o > 0; o >>= 1) s += __shfl_xor_sync(0xffffffffu, s, o);
        float inv = 1.0f / s;
        float q0 = e0 * inv, q1 = e1 * inv;
        size_t g = base + (size_t)(s0 + r) * DK;
        bf16 h0 = __float2bfloat16(q0), h1 = __float2bfloat16(q1);
        Mhi[g + lane]      = h0;
        Mhi[g + lane + 32] = h1;
        Mlo[g + lane]      = __float2bfloat16(q0 - __bfloat162float(h0));
        Mlo[g + lane + 32] = __float2bfloat16(q1 - __bfloat162float(h1));
    }
}

// ===========================================================================
// Launch
// ===========================================================================
extern "C" void kernel_launch(void* const* d_in, const int* in_sizes, int n_in,
                              void* d_out, int out_size)
{
    const float* x  = (const float*)d_in[0];
    const float* Wq = (const float*)d_in[1];
    const float* bq = (const float*)d_in[2];
    const float* Wk = (const float*)d_in[3];
    const float* bk = (const float*)d_in[4];
    const float* Wv = (const float*)d_in[5];
    const float* bv = (const float*)d_in[6];
    const float* Wo = (const float*)d_in[7];
    const float* bo = (const float*)d_in[8];
    const float* Wf = (const float*)d_in[9];
    const float* bf_ = (const float*)d_in[10];
    float* out = (float*)d_out;

    bf16 *xhi, *xlo, *Whi, *Wlo, *WoThi, *WoTlo, *Wchi, *Wclo;
    bf16 *Qhi, *Qlo, *Khi, *Klo, *Vhi, *Vlo, *Mhi, *Mlo;
    float *bp, *zb;
    cudaGetSymbolAddress((void**)&xhi, g_xhi); cudaGetSymbolAddress((void**)&xlo, g_xlo);
    cudaGetSymbolAddress((void**)&Whi, g_Whi); cudaGetSymbolAddress((void**)&Wlo, g_Wlo);
    cudaGetSymbolAddress((void**)&WoThi, g_WoThi); cudaGetSymbolAddress((void**)&WoTlo, g_WoTlo);
    cudaGetSymbolAddress((void**)&Wchi, g_Wchi); cudaGetSymbolAddress((void**)&Wclo, g_Wclo);
    cudaGetSymbolAddress((void**)&Qhi, g_Qhi); cudaGetSymbolAddress((void**)&Qlo, g_Qlo);
    cudaGetSymbolAddress((void**)&Khi, g_Khi); cudaGetSymbolAddress((void**)&Klo, g_Klo);
    cudaGetSymbolAddress((void**)&Vhi, g_Vhi); cudaGetSymbolAddress((void**)&Vlo, g_Vlo);
    cudaGetSymbolAddress((void**)&Mhi, g_Mhi); cudaGetSymbolAddress((void**)&Mlo, g_Mlo);
    cudaGetSymbolAddress((void**)&bp, g_bp); cudaGetSymbolAddress((void**)&zb, g_zb);

    cudaFuncSetAttribute(mma_gemm, cudaFuncAttributeMaxDynamicSharedMemorySize, GEMM_SMEM);
    cudaFuncSetAttribute(qkv_gemm, cudaFuncAttributeMaxDynamicSharedMemorySize, GEMM_SMEM);
    cudaFuncSetAttribute(attn_mma, cudaFuncAttributeMaxDynamicSharedMemorySize, ATTN_SMEM);

    const int WN = DM * DM;

    // converts + Wo transpose + fused bias
    int n4tot = N4X + 4 * N4W;
    cvt_all<<<(n4tot + 255)/256, 256>>>(x, Wq, Wk, Wv, Wf, xhi, xlo, Whi, Wlo);
    dim3 tgrid(DM/32, DM/32);
    trans_wo<<<tgrid, 256>>>(Wo, WoThi, WoTlo);
    bprime_k<<<DM/8, 256>>>(Wf, bo, bf_, bp);

    // Wc = Wf @ Wo (as Wf @ WoT^T), hi/lo output. grid (12, 6)
    dim3 wcgrid(DM/64, DM/128);
    mma_gemm<<<wcgrid, 256, GEMM_SMEM>>>(Whi + 3*(size_t)WN, Wlo + 3*(size_t)WN,
                                         WoThi, WoTlo, zb, nullptr, Wchi, Wclo);

    // QKV projections
    dim3 qgrid(DM/64, MROWS/128, 3);   // (12, 32, 3)
    qkv_gemm<<<qgrid, 256, GEMM_SMEM>>>(xhi, xlo, Whi, Wlo, bq, bk, bv,
                                        Qhi, Qlo, Khi, Klo, Vhi, Vlo);

    // attention (fused softmax -> M hi/lo)
    dim3 agrid(SEQ/128, BD*NH);        // (16, 24)
    attn_mma<<<agrid, 256, ATTN_SMEM>>>(Qhi, Qlo, Khi, Klo, Vhi, Vlo, Mhi, Mlo);

    // single fused output projection: out = M @ Wc^T + b'
    dim3 ggrid(DM/64, MROWS/128);      // (12, 32)
    mma_gemm<<<ggrid, 256, GEMM_SMEM>>>(Mhi, Mlo, Wchi, Wclo, bp, out, nullptr, nullptr);
}